// round 17
// baseline (speedup 1.0000x reference)
#include <cuda_runtime.h>
#include <cuda_bf16.h>
#include <cstdint>

// ============================================================================
// EdgeAggregatorGATED round 17: wavefront reduction via B-column permutation.
// Edge B image permuted so fragment (p, 2*tig+j) -> actual col 16*tig + 2p + j.
// Thread then owns 16 CONSECUTIVE output cols across p-blocks; epilogue drains
// every 2 p-blocks with float4 kd, 2x float4 qv, red.v4 (kd + RED instruction
// count halved). Node kernel / tables unchanged.
// ============================================================================

#define MAXN 51200
__device__ float g_kx[MAXN * 64];
__device__ float g_qv[MAXN * 128];   // interleaved [q,v] per column
__device__ uint4 g_Bpack[1024];      // edge B image (permuted), 16KB
__device__ uint4 g_BpackN[4096];     // node B image, 64KB

__device__ __forceinline__ float fast_sigmoid(float s) {
    return __fdividef(1.0f, 1.0f + __expf(-s));
}
__device__ __forceinline__ unsigned smem_u32(const void* p) {
    return (unsigned)__cvta_generic_to_shared(p);
}
__device__ __forceinline__ uint32_t bf2(float a, float b) {
    uint32_t r; asm("cvt.rn.bf16x2.f32 %0, %1, %2;" : "=r"(r) : "f"(b), "f"(a));
    return r;
}
__device__ __forceinline__ float2 bf2_back(uint32_t h) {
    return make_float2(__uint_as_float(h << 16), __uint_as_float(h & 0xffff0000u));
}
__device__ __forceinline__ void split2(float a, float b, uint32_t& hi, uint32_t& lo) {
    hi = bf2(a, b);
    float2 hb = bf2_back(hi);
    lo = bf2(a - hb.x, b - hb.y);
}
__device__ __forceinline__ void mma_bf16(float c[4], const uint32_t a[4],
                                         uint32_t b0, uint32_t b1) {
    asm volatile(
        "mma.sync.aligned.m16n8k16.row.col.f32.bf16.bf16.f32 "
        "{%0,%1,%2,%3}, {%4,%5,%6,%7}, {%8,%9}, {%0,%1,%2,%3};"
        : "+f"(c[0]), "+f"(c[1]), "+f"(c[2]), "+f"(c[3])
        : "r"(a[0]), "r"(a[1]), "r"(a[2]), "r"(a[3]), "r"(b0), "r"(b1));
}

// Steering kernel: keeps edge_kernel at launch position 4 for ncu capture.
__global__ void nop_kernel() {}

// ----------------------------------------------------------------------------
// bpack (3 blocks x 256).
// Block 0 (edge B, PERMUTED): slot s=(nt*2+kt)*32+lane; i=lane>>2 (B frag
//   n-position), k0=kt*16+2*(lane&3). Actual column:
//     nt<8  (gate):  n_act = 16*(i>>1) + 2*nt + (i&1)          (0..63)
//     nt>=8 (value): n_act = 16*(i>>1) + 2*(nt-8) + (i&1) + 64 (64..127)
// Blocks 1,2 (node B): unchanged layout (kx|qx|vx|skip).
// ----------------------------------------------------------------------------
__global__ void bpack_kernel(const float* __restrict__ Wk,
                             const float* __restrict__ Wq,
                             const float* __restrict__ Wv,
                             const float* __restrict__ Wskip)
{
    int t = threadIdx.x;
    if (blockIdx.x == 0) {
        #pragma unroll
        for (int i4 = 0; i4 < 4; ++i4) {
            int s = t * 4 + i4;
            int nt = s >> 6;
            int kt = (s >> 5) & 1;
            int lane = s & 31;
            int i = lane >> 2;
            int k0 = kt * 16 + 2 * (lane & 3);
            int p = (nt < 8) ? nt : nt - 8;
            int n_act = 16 * (i >> 1) + 2 * p + (i & 1);
            float f[4];
            #pragma unroll
            for (int j = 0; j < 4; ++j) {
                int k = k0 + (j >> 1) * 8 + (j & 1);
                f[j] = (nt < 8)
                    ? (Wk[(64 + k) * 64 + n_act] + Wq[(64 + k) * 64 + n_act])
                    : Wv[(64 + k) * 64 + n_act];
            }
            uint32_t b0h, b0l, b1h, b1l;
            split2(f[0], f[1], b0h, b0l);
            split2(f[2], f[3], b1h, b1l);
            g_Bpack[s] = make_uint4(b0h, b1h, b0l, b1l);
        }
    } else {
        int base = (blockIdx.x - 1) * 2048;
        #pragma unroll
        for (int i4 = 0; i4 < 8; ++i4) {
            int s = base + t * 8 + i4;
            int nt = s >> 7;
            int kt = (s >> 5) & 3;
            int lane = s & 31;
            int n = nt * 8 + (lane >> 2);
            int k0 = kt * 16 + 2 * (lane & 3);
            const float* W = (n < 64) ? Wk : (n < 128) ? Wq : (n < 192) ? Wv : Wskip;
            int nc = n & 63;
            float f[4];
            #pragma unroll
            for (int j = 0; j < 4; ++j) {
                int k = k0 + (j >> 1) * 8 + (j & 1);
                f[j] = W[k * 64 + nc];
            }
            uint32_t b0h, b0l, b1h, b1l;
            split2(f[0], f[1], b0h, b0l);
            split2(f[2], f[3], b1h, b1l);
            g_BpackN[s] = make_uint4(b0h, b1h, b0l, b1l);
        }
    }
}

// ----------------------------------------------------------------------------
// Node kernel (unchanged from R15/16).
// ----------------------------------------------------------------------------
__global__ __launch_bounds__(256, 2) void node_kernel(
    const float* __restrict__ x,
    const float* __restrict__ bk, const float* __restrict__ bq,
    const float* __restrict__ bv, const float* __restrict__ bias,
    float* __restrict__ out, int N)
{
    __shared__ uint4 sB[2048];   // 32KB

    const int tid  = threadIdx.x;
    const int w    = tid >> 5;
    const int lane = tid & 31;
    const int g    = lane >> 2;
    const int tig  = lane & 3;
    const int half = blockIdx.y;

    {
        unsigned sb = smem_u32(sB);
        const uint4* src = g_BpackN + half * 2048;
        #pragma unroll
        for (int i = 0; i < 8; ++i) {
            int idx = tid * 8 + i;
            asm volatile("cp.async.cg.shared.global [%0], [%1], 16;"
                         :: "r"(sb + idx * 16), "l"(src + idx));
        }
        asm volatile("cp.async.commit_group;");
    }

    const int nbase = blockIdx.x * 128;
    int n0 = nbase + w * 16 + g;
    int n1 = n0 + 8;
    const bool v0 = (n0 < N), v1 = (n1 < N);
    const int n0c = v0 ? n0 : N - 1;
    const int n1c = v1 ? n1 : N - 1;

    uint32_t ah[4][4], al[4][4];
    #pragma unroll
    for (int kt = 0; kt < 4; ++kt) {
        const int k0 = kt * 16 + 2 * tig;
        float2 p0 = *(const float2*)(x + (size_t)n0c * 64 + k0);
        float2 p1 = *(const float2*)(x + (size_t)n1c * 64 + k0);
        float2 p2 = *(const float2*)(x + (size_t)n0c * 64 + k0 + 8);
        float2 p3 = *(const float2*)(x + (size_t)n1c * 64 + k0 + 8);
        split2(p0.x, p0.y, ah[kt][0], al[kt][0]);
        split2(p1.x, p1.y, ah[kt][1], al[kt][1]);
        split2(p2.x, p2.y, ah[kt][2], al[kt][2]);
        split2(p3.x, p3.y, ah[kt][3], al[kt][3]);
    }

    asm volatile("cp.async.wait_group 0;");
    __syncthreads();

    #pragma unroll
    for (int p = 0; p < 16; ++p) {
        float c[4] = {0.f, 0.f, 0.f, 0.f};
        #pragma unroll
        for (int kt = 0; kt < 4; ++kt) {
            uint4 B = sB[(p * 4 + kt) * 32 + lane];
            mma_bf16(c, ah[kt], B.x, B.y);
            mma_bf16(c, ah[kt], B.z, B.w);
            mma_bf16(c, al[kt], B.x, B.y);
        }
        const int cc = 8 * p + 2 * tig;
        if (half == 0) {
            if (p < 8) {
                float2 a = *(const float2*)(bk + cc);
                float2 b = *(const float2*)(bq + cc);
                if (v0) *(float2*)(g_kx + (size_t)n0 * 64 + cc) =
                    make_float2(c[0] + a.x + b.x, c[1] + a.y + b.y);
                if (v1) *(float2*)(g_kx + (size_t)n1 * 64 + cc) =
                    make_float2(c[2] + a.x + b.x, c[3] + a.y + b.y);
            } else {
                int col = cc - 64;
                if (v0) {
                    g_qv[(size_t)n0 * 128 + 2 * col] = c[0];
                    g_qv[(size_t)n0 * 128 + 2 * col + 2] = c[1];
                }
                if (v1) {
                    g_qv[(size_t)n1 * 128 + 2 * col] = c[2];
                    g_qv[(size_t)n1 * 128 + 2 * col + 2] = c[3];
                }
            }
        } else {
            if (p < 8) {
                float2 b = *(const float2*)(bv + cc);
                if (v0) {
                    g_qv[(size_t)n0 * 128 + 2 * cc + 1] = c[0] + b.x;
                    g_qv[(size_t)n0 * 128 + 2 * cc + 3] = c[1] + b.y;
                }
                if (v1) {
                    g_qv[(size_t)n1 * 128 + 2 * cc + 1] = c[2] + b.x;
                    g_qv[(size_t)n1 * 128 + 2 * cc + 3] = c[3] + b.y;
                }
            } else {
                int col = cc - 64;
                float2 b = *(const float2*)(bias + col);
                if (v0) *(float2*)(out + (size_t)n0 * 64 + col) =
                    make_float2(c[0] + b.x, c[1] + b.y);
                if (v1) *(float2*)(out + (size_t)n1 * 64 + col) =
                    make_float2(c[2] + b.x, c[3] + b.y);
            }
        }
    }
}

// ----------------------------------------------------------------------------
// Edge kernel: permuted-column drain. Chunk c (p-blocks 2c,2c+1) covers this
// thread's actual cols [16*tig+4c, +4): float4 kd, 2x float4 qv, red.v4.
// ----------------------------------------------------------------------------
#define TILE_E 128

__global__ __launch_bounds__(256, 3) void edge_kernel(
    const float* __restrict__ ea,
    const int* __restrict__ srcArr, const int* __restrict__ dstArr,
    float* __restrict__ out, int E)
{
    __shared__ uint4 sB[1024];   // 16KB

    const int tid  = threadIdx.x;
    const int w    = tid >> 5;
    const int lane = tid & 31;
    const int g    = lane >> 2;
    const int tig  = lane & 3;

    {
        unsigned sb = smem_u32(sB);
        #pragma unroll
        for (int i = 0; i < 4; ++i) {
            int idx = tid * 4 + i;
            asm volatile("cp.async.cg.shared.global [%0], [%1], 16;"
                         :: "r"(sb + idx * 16), "l"(g_Bpack + idx));
        }
        asm volatile("cp.async.commit_group;");
    }

    const long ebase = (long)blockIdx.x * TILE_E;
    long e0 = ebase + w * 16 + g;
    long e1 = e0 + 8;
    const bool v0 = (e0 < (long)E), v1 = (e1 < (long)E);
    const long e0c = v0 ? e0 : (long)E - 1;
    const long e1c = v1 ? e1 : (long)E - 1;

    uint32_t ah[2][4], al[2][4];
    #pragma unroll
    for (int kt = 0; kt < 2; ++kt) {
        const int k0 = kt * 16 + 2 * tig;
        float2 p0 = *(const float2*)(ea + e0c * 32 + k0);
        float2 p1 = *(const float2*)(ea + e1c * 32 + k0);
        float2 p2 = *(const float2*)(ea + e0c * 32 + k0 + 8);
        float2 p3 = *(const float2*)(ea + e1c * 32 + k0 + 8);
        split2(p0.x, p0.y, ah[kt][0], al[kt][0]);
        split2(p1.x, p1.y, ah[kt][1], al[kt][1]);
        split2(p2.x, p2.y, ah[kt][2], al[kt][2]);
        split2(p3.x, p3.y, ah[kt][3], al[kt][3]);
    }

    const int dst0 = dstArr[e0c], src0 = srcArr[e0c];
    const int dst1 = dstArr[e1c], src1 = srcArr[e1c];
    const float* kx0 = g_kx + (size_t)dst0 * 64 + 16 * tig;
    const float* qv0 = g_qv + (size_t)src0 * 128 + 32 * tig;
    const float* kx1 = g_kx + (size_t)dst1 * 64 + 16 * tig;
    const float* qv1 = g_qv + (size_t)src1 * 128 + 32 * tig;
    float* o0 = out + (size_t)dst0 * 64 + 16 * tig;
    float* o1 = out + (size_t)dst1 * 64 + 16 * tig;

    asm volatile("cp.async.wait_group 0;");
    __syncthreads();

    #pragma unroll
    for (int c = 0; c < 4; ++c) {
        // Gathers for this chunk (independent of MMA results — scheduler can
        // hoist them over the MMAs).
        float4 kd0 = *(const float4*)(kx0 + 4 * c);
        float4 kd1 = *(const float4*)(kx1 + 4 * c);
        float4 a00 = *(const float4*)(qv0 + 8 * c);      // {q0,v0,q1,v1}
        float4 a01 = *(const float4*)(qv0 + 8 * c + 4);  // {q2,v2,q3,v3}
        float4 a10 = *(const float4*)(qv1 + 8 * c);
        float4 a11 = *(const float4*)(qv1 + 8 * c + 4);

        float cg[2][4], cv[2][4];
        #pragma unroll
        for (int pp = 0; pp < 2; ++pp) {
            const int p = 2 * c + pp;
            cg[pp][0]=0.f; cg[pp][1]=0.f; cg[pp][2]=0.f; cg[pp][3]=0.f;
            cv[pp][0]=0.f; cv[pp][1]=0.f; cv[pp][2]=0.f; cv[pp][3]=0.f;
            #pragma unroll
            for (int kt = 0; kt < 2; ++kt) {
                uint4 Bg = sB[(p * 2 + kt) * 32 + lane];
                uint4 Bv = sB[((p + 8) * 2 + kt) * 32 + lane];
                mma_bf16(cg[pp], ah[kt], Bg.x, Bg.y);
                mma_bf16(cg[pp], ah[kt], Bg.z, Bg.w);
                mma_bf16(cg[pp], al[kt], Bg.x, Bg.y);
                mma_bf16(cv[pp], ah[kt], Bv.x, Bv.y);
                mma_bf16(cv[pp], ah[kt], Bv.z, Bv.w);
                mma_bf16(cv[pp], al[kt], Bv.x, Bv.y);
            }
        }

        // Drain: row e0 = {cg[0][0],cg[0][1],cg[1][0],cg[1][1]} at cols
        // 16tig+4c .. +3; row e1 uses indices [2],[3].
        float m0 = fast_sigmoid(cg[0][0] + kd0.x + a00.x) * (cv[0][0] + a00.y);
        float m1 = fast_sigmoid(cg[0][1] + kd0.y + a00.z) * (cv[0][1] + a00.w);
        float m2 = fast_sigmoid(cg[1][0] + kd0.z + a01.x) * (cv[1][0] + a01.y);
        float m3 = fast_sigmoid(cg[1][1] + kd0.w + a01.z) * (cv[1][1] + a01.w);
        float n0 = fast_sigmoid(cg[0][2] + kd1.x + a10.x) * (cv[0][2] + a10.y);
        float n1 = fast_sigmoid(cg[0][3] + kd1.y + a10.z) * (cv[0][3] + a10.w);
        float n2 = fast_sigmoid(cg[1][2] + kd1.z + a11.x) * (cv[1][2] + a11.y);
        float n3 = fast_sigmoid(cg[1][3] + kd1.w + a11.z) * (cv[1][3] + a11.w);
        if (v0)
            asm volatile("red.global.add.v4.f32 [%0], {%1,%2,%3,%4};"
                         :: "l"(o0 + 4 * c), "f"(m0), "f"(m1), "f"(m2), "f"(m3)
                         : "memory");
        if (v1)
            asm volatile("red.global.add.v4.f32 [%0], {%1,%2,%3,%4};"
                         :: "l"(o1 + 4 * c), "f"(n0), "f"(n1), "f"(n2), "f"(n3)
                         : "memory");
    }
}

// ----------------------------------------------------------------------------
// Launch. Inputs: x, edge_index, edge_attr, Wk, bk, Wq, bq, Wv, bv, Wskip, bias.
// ----------------------------------------------------------------------------
extern "C" void kernel_launch(void* const* d_in, const int* in_sizes, int n_in,
                              void* d_out, int out_size)
{
    const float* x     = (const float*)d_in[0];
    const int*   ei    = (const int*)d_in[1];
    const float* ea    = (const float*)d_in[2];
    const float* Wk    = (const float*)d_in[3];
    const float* bk    = (const float*)d_in[4];
    const float* Wq    = (const float*)d_in[5];
    const float* bq    = (const float*)d_in[6];
    const float* Wv    = (const float*)d_in[7];
    const float* bv    = (const float*)d_in[8];
    const float* Wskip = (const float*)d_in[9];
    const float* bias  = (const float*)d_in[10];
    float* out = (float*)d_out;

    int N = in_sizes[0] / 64;   // x is [N, 64]
    int E = in_sizes[2] / 32;   // edge_attr is [E, 32]

    nop_kernel<<<1, 32>>>();    // steers bounded ncu capture onto edge_kernel

    bpack_kernel<<<3, 256>>>(Wk, Wq, Wv, Wskip);

    dim3 ngrid((N + 127) / 128, 2);
    node_kernel<<<ngrid, 256>>>(x, bk, bq, bv, bias, out, N);

    int numTiles = (E + TILE_E - 1) / TILE_E;
    edge_kernel<<<numTiles, 256>>>(ea, ei, ei + E, out, E);
}